// round 15
// baseline (speedup 1.0000x reference)
#include <cuda_runtime.h>
#include <cstdint>

#define NUM_LEVELS 16
#define LOG2_T 19
#define TABLE_SIZE (1u << LOG2_T)
#define TABLE_MASK (TABLE_SIZE - 1u)
#define P1 2654435761u
#define P2 805459861u

// FOUR half-items per thread, same point: levels {l, l+4, l+8, l+12} for one
// (point, half). p = tid>>3, lbase = (tid>>1)&3, half = tid&1.
// Point loaded + normalized once per thread. x-prime is 1 -> even-ix corner
// pair {ix,ix+1} = aligned table slots {2m,2m+1}: one float4 fetches both.
// Per thread: 8 LDG.128 + 8 @p-predicated LDG.64, ALL front-batched.
// Phase 3 RECOMPUTES fracs/weights from the retained x0..x2 so only the
// load payload + 1 packed mask stay live across the batch (fits 64 regs).
__global__ __launch_bounds__(256, 4) void hashenc_kernel(
    const float* __restrict__ x,
    const float* __restrict__ tables,
    float* __restrict__ out,
    int N)
{
    int tid = blockIdx.x * blockDim.x + threadIdx.x;
    if (tid >= N * 8) return;          // exact grid -> never taken
    int p     = tid >> 3;
    int lbase = (tid >> 1) & 3;
    int half  = tid & 1;

    // one point per thread; 8 consecutive threads share it -> broadcast
    float x0 = x[p * 3 + 0];
    float x1 = x[p * 3 + 1];
    float x2 = x[p * 3 + 2];

    const float hi = 1.0f - 1e-6f;
    x0 = fminf(fmaxf((x0 + 1.0f) * 0.5f, 0.0f), hi);
    x1 = fminf(fmaxf((x1 + 1.0f) * 0.5f, 0.0f), hi);
    x2 = fminf(fmaxf((x2 + 1.0f) * 0.5f, 0.0f), hi);

    float4  q[4][2];
    float   eox[4][2], eoy[4][2];
    // bits 2k / 2k+1: parity of i00/i01 for level-slot k; bits 8+k: odd(ix)
    uint32_t mask = 0;

    // ---- phase 1+2: index math and ALL loads, 4 levels ----
#pragma unroll
    for (int k = 0; k < 4; k++) {
        int l = lbase + 4 * k;

        float res = (float)(16 << l);
        float s0 = x0 * res, s1 = x1 * res, s2 = x2 * res;
        uint32_t ix = (uint32_t)(int)floorf(s0);
        uint32_t iy = (uint32_t)(int)floorf(s1);
        uint32_t iz = (uint32_t)(int)floorf(s2);

        uint32_t ay = (iy + (uint32_t)half) * P1;
        uint32_t K0 = ay ^ (iz * P2) ^ (uint32_t)l;          // (y, z0)
        uint32_t K1 = ay ^ ((iz + 1u) * P2) ^ (uint32_t)l;   // (y, z1)

        const float2* __restrict__ tbl  = (const float2*)tables + (size_t)l * TABLE_SIZE;
        const float4* __restrict__ tbl4 = (const float4*)tbl;

        uint32_t oddu = ix & 1u;
        uint32_t ix1 = ix + 1u;
        uint32_t i00 = (ix ^ K0) & TABLE_MASK;
        uint32_t i01 = (ix ^ K1) & TABLE_MASK;

        mask |= (i00 & 1u) << (2 * k);
        mask |= (i01 & 1u) << (2 * k + 1);
        mask |= oddu << (8 + k);

        q[k][0] = __ldg(&tbl4[i00 >> 1]);
        q[k][1] = __ldg(&tbl4[i01 >> 1]);

        // predicated odd-x gathers; outputs are dead when !odd -> no zero-init
        const float2* a0 = &tbl[(ix1 ^ K0) & TABLE_MASK];
        const float2* a1 = &tbl[(ix1 ^ K1) & TABLE_MASK];
        asm("{\n\t"
            ".reg .pred p;\n\t"
            "setp.ne.u32 p, %4, 0;\n\t"
            "@p ld.global.nc.v2.f32 {%0, %1}, [%5];\n\t"
            "@p ld.global.nc.v2.f32 {%2, %3}, [%6];\n\t"
            "}"
            : "=f"(eox[k][0]), "=f"(eoy[k][0]), "=f"(eox[k][1]), "=f"(eoy[k][1])
            : "r"(oddu), "l"(a0), "l"(a1));
    }

    // ---- phase 3: recompute weights, combine, pair-reduce, store ----
    float2* orow = (float2*)(out + (size_t)p * (NUM_LEVELS * 2));
#pragma unroll
    for (int k = 0; k < 4; k++) {
        int l = lbase + 4 * k;

        float res = (float)(16 << l);
        float s0 = x0 * res, s1 = x1 * res, s2 = x2 * res;
        float fx = s0 - floorf(s0);
        float fy = s1 - floorf(s1);
        float fz = s2 - floorf(s2);
        float gx = 1.0f - fx, gz = 1.0f - fz;
        float wy = half ? fy : (1.0f - fy);
        float wA = wy * gz;
        float wB = wy * fz;

        bool odd = ((mask >> (8 + k)) & 1u) != 0u;
        float o0 = 0.0f, o1 = 0.0f;
#define COMBINE(Q, EOX, EOY, SELBIT, W)                          \
        {                                                        \
            bool sel = ((mask >> (SELBIT)) & 1u) != 0u;          \
            float e0x = sel ? Q.z : Q.x;                         \
            float e0y = sel ? Q.w : Q.y;                         \
            float epx = sel ? Q.x : Q.z;                         \
            float epy = sel ? Q.y : Q.w;                         \
            float e4x = odd ? EOX : epx;                         \
            float e4y = odd ? EOY : epy;                         \
            o0 += (e0x * gx + e4x * fx) * W;                     \
            o1 += (e0y * gx + e4y * fx) * W;                     \
        }
        COMBINE(q[k][0], eox[k][0], eoy[k][0], 2 * k,     wA)
        COMBINE(q[k][1], eox[k][1], eoy[k][1], 2 * k + 1, wB)
#undef COMBINE

        // lanes (2m, 2m+1) hold the two y-halves of one item
        o0 += __shfl_xor_sync(0xFFFFFFFFu, o0, 1);
        o1 += __shfl_xor_sync(0xFFFFFFFFu, o1, 1);

        if (half == 0) {
            orow[l] = make_float2(o0, o1);
        }
    }
}

extern "C" void kernel_launch(void* const* d_in, const int* in_sizes, int n_in,
                              void* d_out, int out_size) {
    const float* x      = (const float*)d_in[0];
    const float* tables = (const float*)d_in[1];
    float* out          = (float*)d_out;
    int N = in_sizes[0] / 3;

    int threads = 256;
    int total_threads = N * 8;            // one thread per 4 half-items
    int blocks = (total_threads + threads - 1) / threads;
    hashenc_kernel<<<blocks, threads>>>(x, tables, out, N);
}

// round 16
// speedup vs baseline: 1.0218x; 1.0218x over previous
#include <cuda_runtime.h>
#include <cstdint>

#define NUM_LEVELS 16
#define LOG2_T 19
#define TABLE_SIZE (1u << LOG2_T)
#define TABLE_MASK (TABLE_SIZE - 1u)
#define P1 2654435761u
#define P2 805459861u

// Best operating point (R14, 150.3 us) + dead zero-init movs removed from the
// predicated loads (validated in R15). Two half-items per thread, SAME point:
// (p, l, half) and (p, l+8, half); p = tid>>4, l = (tid>>1)&7, half = tid&1.
// x-prime is 1 -> even-ix corner pair {ix,ix+1} occupies aligned table slots
// {2m,2m+1}: one float4 fetches both corners. Per thread: 4 LDG.128 +
// 4 @p-predicated LDG.64, ALL issued before any combine (51-reg budget).
// Runs at the L1tex gather-wavefront floor (~50M wavefronts).
__global__ __launch_bounds__(256, 5) void hashenc_kernel(
    const float* __restrict__ x,
    const float* __restrict__ tables,
    float* __restrict__ out,
    int N)
{
    int tid = blockIdx.x * blockDim.x + threadIdx.x;
    if (tid >= N * NUM_LEVELS) return;     // exact grid -> never taken
    int p     = tid >> 4;
    int lbase = (tid >> 1) & 7;
    int half  = tid & 1;

    // one point per thread; 16 consecutive threads share it -> broadcast
    float x0 = x[p * 3 + 0];
    float x1 = x[p * 3 + 1];
    float x2 = x[p * 3 + 2];

    const float hi = 1.0f - 1e-6f;
    x0 = fminf(fmaxf((x0 + 1.0f) * 0.5f, 0.0f), hi);
    x1 = fminf(fmaxf((x1 + 1.0f) * 0.5f, 0.0f), hi);
    x2 = fminf(fmaxf((x2 + 1.0f) * 0.5f, 0.0f), hi);

    float4  q[2][2];
    float   eox[2][2], eoy[2][2];
    uint32_t i00[2], i01[2], oddu[2];
    float   fxv[2], wA[2], wB[2];

    // ---- phase 1+2: index math and ALL loads, both levels ----
#pragma unroll
    for (int k = 0; k < 2; k++) {
        int l = lbase + 8 * k;

        float res = (float)(16 << l);
        float s0 = x0 * res, s1 = x1 * res, s2 = x2 * res;
        float f0 = floorf(s0), f1 = floorf(s1), f2 = floorf(s2);
        float fx = s0 - f0, fy = s1 - f1, fz = s2 - f2;
        uint32_t ix = (uint32_t)(int)f0;
        uint32_t iy = (uint32_t)(int)f1;
        uint32_t iz = (uint32_t)(int)f2;

        uint32_t ay = (iy + (uint32_t)half) * P1;
        uint32_t K0 = ay ^ (iz * P2) ^ (uint32_t)l;          // (y, z0)
        uint32_t K1 = ay ^ ((iz + 1u) * P2) ^ (uint32_t)l;   // (y, z1)

        const float2* __restrict__ tbl  = (const float2*)tables + (size_t)l * TABLE_SIZE;
        const float4* __restrict__ tbl4 = (const float4*)tbl;

        oddu[k] = ix & 1u;
        uint32_t ix1 = ix + 1u;

        i00[k] = (ix ^ K0) & TABLE_MASK;
        i01[k] = (ix ^ K1) & TABLE_MASK;

        q[k][0] = __ldg(&tbl4[i00[k] >> 1]);
        q[k][1] = __ldg(&tbl4[i01[k] >> 1]);

        // predicated odd-x gathers; outputs are dead when !odd -> no zero-init
        const float2* a0 = &tbl[(ix1 ^ K0) & TABLE_MASK];
        const float2* a1 = &tbl[(ix1 ^ K1) & TABLE_MASK];
        asm("{\n\t"
            ".reg .pred p;\n\t"
            "setp.ne.u32 p, %4, 0;\n\t"
            "@p ld.global.nc.v2.f32 {%0, %1}, [%5];\n\t"
            "@p ld.global.nc.v2.f32 {%2, %3}, [%6];\n\t"
            "}"
            : "=f"(eox[k][0]), "=f"(eoy[k][0]), "=f"(eox[k][1]), "=f"(eoy[k][1])
            : "r"(oddu[k]), "l"(a0), "l"(a1));

        float gz = 1.0f - fz;
        float wy = half ? fy : (1.0f - fy);
        fxv[k] = fx;
        wA[k] = wy * gz;
        wB[k] = wy * fz;
    }

    // ---- phase 3: combine + pair-reduce + store, both levels ----
    float2* orow = (float2*)(out + (size_t)p * (NUM_LEVELS * 2));
#pragma unroll
    for (int k = 0; k < 2; k++) {
        bool odd = oddu[k] != 0u;
        float fx = fxv[k];
        float gx = 1.0f - fx;
        float o0 = 0.0f, o1 = 0.0f;
#define COMBINE(Q, EOX, EOY, I0, W)                              \
        {                                                        \
            bool sel = (I0 & 1u) != 0u;                          \
            float e0x = sel ? Q.z : Q.x;                         \
            float e0y = sel ? Q.w : Q.y;                         \
            float epx = sel ? Q.x : Q.z;                         \
            float epy = sel ? Q.y : Q.w;                         \
            float e4x = odd ? EOX : epx;                         \
            float e4y = odd ? EOY : epy;                         \
            o0 += (e0x * gx + e4x * fx) * W;                     \
            o1 += (e0y * gx + e4y * fx) * W;                     \
        }
        COMBINE(q[k][0], eox[k][0], eoy[k][0], i00[k], wA[k])
        COMBINE(q[k][1], eox[k][1], eoy[k][1], i01[k], wB[k])
#undef COMBINE

        // lanes (2m, 2m+1) hold the two y-halves of one item
        o0 += __shfl_xor_sync(0xFFFFFFFFu, o0, 1);
        o1 += __shfl_xor_sync(0xFFFFFFFFu, o1, 1);

        if (half == 0) {
            orow[lbase + 8 * k] = make_float2(o0, o1);
        }
    }
}

extern "C" void kernel_launch(void* const* d_in, const int* in_sizes, int n_in,
                              void* d_out, int out_size) {
    const float* x      = (const float*)d_in[0];
    const float* tables = (const float*)d_in[1];
    float* out          = (float*)d_out;
    int N = in_sizes[0] / 3;

    int threads = 256;
    int total_threads = N * NUM_LEVELS;           // one thread per 2 half-items
    int blocks = (total_threads + threads - 1) / threads;
    hashenc_kernel<<<blocks, threads>>>(x, tables, out, N);
}

// round 17
// speedup vs baseline: 1.0821x; 1.0590x over previous
#include <cuda_runtime.h>
#include <cstdint>

#define NUM_LEVELS 16
#define LOG2_T 19
#define TABLE_SIZE (1u << LOG2_T)
#define TABLE_MASK (TABLE_SIZE - 1u)
#define P1 2654435761u
#define P2 805459861u

// FINAL: exact R14 configuration (measured best, 150.3 us).
// Two half-items per thread, SAME point: (p, l, half) and (p, l+8, half);
// p = tid>>4, l = (tid>>1)&7, half = tid&1. Point loaded + normalized once.
// x-prime is 1 -> even-ix corner pair {ix,ix+1} occupies aligned table slots
// {2m,2m+1}: one float4 fetches both corners. Per thread: 4 LDG.128 +
// 4 @p-predicated LDG.64 (WITH zero-init movs — removing them regressed the
// SASS schedule by 8 us in R16), ALL issued before any combine under a
// 51-reg budget. Runs at the L1tex gather-wavefront floor (~50M wavefronts).
__global__ __launch_bounds__(256, 5) void hashenc_kernel(
    const float* __restrict__ x,
    const float* __restrict__ tables,
    float* __restrict__ out,
    int N)
{
    int tid = blockIdx.x * blockDim.x + threadIdx.x;
    if (tid >= N * NUM_LEVELS) return;     // exact grid -> never taken
    int p     = tid >> 4;
    int lbase = (tid >> 1) & 7;
    int half  = tid & 1;

    // one point per thread; 16 consecutive threads share it -> broadcast
    float x0 = x[p * 3 + 0];
    float x1 = x[p * 3 + 1];
    float x2 = x[p * 3 + 2];

    const float hi = 1.0f - 1e-6f;
    x0 = fminf(fmaxf((x0 + 1.0f) * 0.5f, 0.0f), hi);
    x1 = fminf(fmaxf((x1 + 1.0f) * 0.5f, 0.0f), hi);
    x2 = fminf(fmaxf((x2 + 1.0f) * 0.5f, 0.0f), hi);

    float4  q[2][2];
    float   eox[2][2], eoy[2][2];
    uint32_t i00[2], i01[2], oddu[2];
    float   fxv[2], wA[2], wB[2];

    // ---- phase 1+2: index math and ALL loads, both levels ----
#pragma unroll
    for (int k = 0; k < 2; k++) {
        int l = lbase + 8 * k;

        float res = (float)(16 << l);
        float s0 = x0 * res, s1 = x1 * res, s2 = x2 * res;
        float f0 = floorf(s0), f1 = floorf(s1), f2 = floorf(s2);
        float fx = s0 - f0, fy = s1 - f1, fz = s2 - f2;
        uint32_t ix = (uint32_t)(int)f0;
        uint32_t iy = (uint32_t)(int)f1;
        uint32_t iz = (uint32_t)(int)f2;

        uint32_t ay = (iy + (uint32_t)half) * P1;
        uint32_t K0 = ay ^ (iz * P2) ^ (uint32_t)l;          // (y, z0)
        uint32_t K1 = ay ^ ((iz + 1u) * P2) ^ (uint32_t)l;   // (y, z1)

        const float2* __restrict__ tbl  = (const float2*)tables + (size_t)l * TABLE_SIZE;
        const float4* __restrict__ tbl4 = (const float4*)tbl;

        oddu[k] = ix & 1u;
        uint32_t ix1 = ix + 1u;

        i00[k] = (ix ^ K0) & TABLE_MASK;
        i01[k] = (ix ^ K1) & TABLE_MASK;

        q[k][0] = __ldg(&tbl4[i00[k] >> 1]);
        q[k][1] = __ldg(&tbl4[i01[k] >> 1]);

        const float2* a0 = &tbl[(ix1 ^ K0) & TABLE_MASK];
        const float2* a1 = &tbl[(ix1 ^ K1) & TABLE_MASK];
        asm("{\n\t"
            ".reg .pred p;\n\t"
            "setp.ne.u32 p, %4, 0;\n\t"
            "mov.f32 %0, 0f00000000;\n\t"
            "mov.f32 %1, 0f00000000;\n\t"
            "mov.f32 %2, 0f00000000;\n\t"
            "mov.f32 %3, 0f00000000;\n\t"
            "@p ld.global.nc.v2.f32 {%0, %1}, [%5];\n\t"
            "@p ld.global.nc.v2.f32 {%2, %3}, [%6];\n\t"
            "}"
            : "=f"(eox[k][0]), "=f"(eoy[k][0]), "=f"(eox[k][1]), "=f"(eoy[k][1])
            : "r"(oddu[k]), "l"(a0), "l"(a1));

        float gz = 1.0f - fz;
        float wy = half ? fy : (1.0f - fy);
        fxv[k] = fx;
        wA[k] = wy * gz;
        wB[k] = wy * fz;
    }

    // ---- phase 3: combine + pair-reduce + store, both levels ----
    float2* orow = (float2*)(out + (size_t)p * (NUM_LEVELS * 2));
#pragma unroll
    for (int k = 0; k < 2; k++) {
        bool odd = oddu[k] != 0u;
        float fx = fxv[k];
        float gx = 1.0f - fx;
        float o0 = 0.0f, o1 = 0.0f;
#define COMBINE(Q, EOX, EOY, I0, W)                              \
        {                                                        \
            bool sel = (I0 & 1u) != 0u;                          \
            float e0x = sel ? Q.z : Q.x;                         \
            float e0y = sel ? Q.w : Q.y;                         \
            float epx = sel ? Q.x : Q.z;                         \
            float epy = sel ? Q.y : Q.w;                         \
            float e4x = odd ? EOX : epx;                         \
            float e4y = odd ? EOY : epy;                         \
            o0 += (e0x * gx + e4x * fx) * W;                     \
            o1 += (e0y * gx + e4y * fx) * W;                     \
        }
        COMBINE(q[k][0], eox[k][0], eoy[k][0], i00[k], wA[k])
        COMBINE(q[k][1], eox[k][1], eoy[k][1], i01[k], wB[k])
#undef COMBINE

        // lanes (2m, 2m+1) hold the two y-halves of one item
        o0 += __shfl_xor_sync(0xFFFFFFFFu, o0, 1);
        o1 += __shfl_xor_sync(0xFFFFFFFFu, o1, 1);

        if (half == 0) {
            orow[lbase + 8 * k] = make_float2(o0, o1);
        }
    }
}

extern "C" void kernel_launch(void* const* d_in, const int* in_sizes, int n_in,
                              void* d_out, int out_size) {
    const float* x      = (const float*)d_in[0];
    const float* tables = (const float*)d_in[1];
    float* out          = (float*)d_out;
    int N = in_sizes[0] / 3;

    int threads = 256;
    int total_threads = N * NUM_LEVELS;           // one thread per 2 half-items
    int blocks = (total_threads + threads - 1) / threads;
    hashenc_kernel<<<blocks, threads>>>(x, tables, out, N);
}